// round 5
// baseline (speedup 1.0000x reference)
#include <cuda_runtime.h>
#include <math_constants.h>

// Shapes (fixed per reference setup_inputs)
#define N_SPATIAL 128           // n
#define DEPTH     2048          // channels
#define NPOS      (N_SPATIAL * N_SPATIAL)     // 16384 spatial positions
#define TOTAL     (NPOS * DEPTH)              // 33,554,432 elements

// Pass-1 tiling
#define NCHUNK    512                          // spatial chunks
#define PS        (NPOS / NCHUNK)              // 32 positions per chunk
#define P1_TPB    256
#define CH_PER_T  4                            // channels per thread (float4)
#define CH_GROUPS (DEPTH / (P1_TPB * CH_PER_T))// 2
#define P1_BATCH  4

// Pass-2 two-level reduce
#define RGROUPS   8
#define RCHUNKS   (NCHUNK / RGROUPS)           // 64

// Pass-3 tiling (chunk stays inside one spatial row -> i constant per CTA)
#define P3_PS     32
#define P3_NCHUNK (NPOS / P3_PS)               // 512
#define P3_BATCH  8

// Scratch (allocation-free: __device__ globals)
__device__ float g_pmax[NCHUNK * DEPTH];
__device__ int   g_pidx[NCHUNK * DEPTH];
__device__ float g_p2max[RGROUPS * DEPTH];
__device__ int   g_p2idx[RGROUPS * DEPTH];
__device__ int   g_argidx[DEPTH];

// merge: a holds the SMALLER index -> '>=' keeps first occurrence
__device__ __forceinline__ void merge_ge(float& ma, int& ia, float mb, int ib)
{
    bool keep = (ma >= mb);
    ma = keep ? ma : mb;
    ia = keep ? ia : ib;
}

// ---------------------------------------------------------------------------
// Pass 1: per-(chunk, channel) partial argmax.
// Default-cached loads: we WANT x allocated and retained in L2 — it's ~the
// size of L2 and is re-read by pass 3 (and by pass 1 of the next replay).
// ---------------------------------------------------------------------------
__global__ void __launch_bounds__(P1_TPB, 5)
partial_argmax_kernel(const float* __restrict__ x)
{
    const int chunk = blockIdx.y;
    const int c4 = (blockIdx.x * P1_TPB + threadIdx.x) * CH_PER_T;
    const int p0 = chunk * PS;

    float m0 = -CUDART_INF_F, m1 = -CUDART_INF_F, m2 = -CUDART_INF_F, m3 = -CUDART_INF_F;
    int i0 = 0, i1 = 0, i2 = 0, i3 = 0;

    const float4* __restrict__ xp =
        reinterpret_cast<const float4*>(x + (size_t)p0 * DEPTH + c4);
    const int stride4 = DEPTH / 4;

    for (int pb = 0; pb < PS; pb += P1_BATCH) {
        float4 b0 = __ldg(xp + (size_t)(pb + 0) * stride4);
        float4 b1 = __ldg(xp + (size_t)(pb + 1) * stride4);
        float4 b2 = __ldg(xp + (size_t)(pb + 2) * stride4);
        float4 b3 = __ldg(xp + (size_t)(pb + 3) * stride4);
        const int q0 = p0 + pb, q1 = q0 + 1, q2 = q0 + 2, q3 = q0 + 3;

        { float ma = b0.x; int ia = q0; merge_ge(ma, ia, b1.x, q1);
          float mb = b2.x; int ib = q2; merge_ge(mb, ib, b3.x, q3);
          merge_ge(ma, ia, mb, ib);
          if (ma > m0) { m0 = ma; i0 = ia; } }
        { float ma = b0.y; int ia = q0; merge_ge(ma, ia, b1.y, q1);
          float mb = b2.y; int ib = q2; merge_ge(mb, ib, b3.y, q3);
          merge_ge(ma, ia, mb, ib);
          if (ma > m1) { m1 = ma; i1 = ia; } }
        { float ma = b0.z; int ia = q0; merge_ge(ma, ia, b1.z, q1);
          float mb = b2.z; int ib = q2; merge_ge(mb, ib, b3.z, q3);
          merge_ge(ma, ia, mb, ib);
          if (ma > m2) { m2 = ma; i2 = ia; } }
        { float ma = b0.w; int ia = q0; merge_ge(ma, ia, b1.w, q1);
          float mb = b2.w; int ib = q2; merge_ge(mb, ib, b3.w, q3);
          merge_ge(ma, ia, mb, ib);
          if (ma > m3) { m3 = ma; i3 = ia; } }
    }

    float* pm = &g_pmax[(size_t)chunk * DEPTH + c4];
    int*   pi = &g_pidx[(size_t)chunk * DEPTH + c4];
    pm[0] = m0; pm[1] = m1; pm[2] = m2; pm[3] = m3;
    pi[0] = i0; pi[1] = i1; pi[2] = i2; pi[3] = i3;
}

// ---------------------------------------------------------------------------
// Pass 2a/2b: fold partials. Ascending chunk order + strict '>' keeps the
// first-occurrence (smallest flat index) among equal maxima.
// Streaming loads: partials are read-once, don't evict x from L2.
// ---------------------------------------------------------------------------
__global__ void __launch_bounds__(256)
reduce_argmax_stage1(void)
{
    const int t = blockIdx.x * blockDim.x + threadIdx.x;
    const int c = t & (DEPTH - 1);
    const int q = t >> 11;

    const int k0 = q * RCHUNKS;
    float best = __ldcs(&g_pmax[(size_t)k0 * DEPTH + c]);
    int   bidx = __ldcs(&g_pidx[(size_t)k0 * DEPTH + c]);
    #pragma unroll 8
    for (int k = 1; k < RCHUNKS; k++) {
        float m = __ldcs(&g_pmax[(size_t)(k0 + k) * DEPTH + c]);
        int   i = __ldcs(&g_pidx[(size_t)(k0 + k) * DEPTH + c]);
        if (m > best) { best = m; bidx = i; }
    }
    g_p2max[(size_t)q * DEPTH + c] = best;
    g_p2idx[(size_t)q * DEPTH + c] = bidx;
}

__global__ void __launch_bounds__(256)
reduce_argmax_stage2(void)
{
    const int c = blockIdx.x * blockDim.x + threadIdx.x;
    float best = g_p2max[c];
    int   bidx = g_p2idx[c];
    #pragma unroll
    for (int q = 1; q < RGROUPS; q++) {
        float m = g_p2max[(size_t)q * DEPTH + c];
        int   i = g_p2idx[(size_t)q * DEPTH + c];
        if (m > best) { best = m; bidx = i; }
    }
    g_argidx[c] = bidx;
}

// ---------------------------------------------------------------------------
// Pass 3: out = x * max(-1, 1 - l1/128) with the reference's transposed
// coords (i_max = idx % 128, j_max = idx / 128).
// Reads default-cached (hit the L2-resident x). Stores WRITE-THROUGH so out
// never leaves dirty L2 lines: no deferred writeback storm into the next
// replay's pass 1, and x residency is preserved across iterations.
// ---------------------------------------------------------------------------
__global__ void __launch_bounds__(P1_TPB)
apply_mask_kernel(const float* __restrict__ x, float* __restrict__ out)
{
    const int chunk = blockIdx.y;                       // 0..511
    const int c4 = (blockIdx.x * P1_TPB + threadIdx.x) * CH_PER_T;
    const int p0 = chunk * P3_PS;
    const int i  = p0 >> 7;                             // row (constant in chunk)
    const int j0 = p0 & 127;                            // starting col

    const float inv_n = 1.0f / (float)N_SPATIAL;

    int4 idx = __ldg(reinterpret_cast<const int4*>(&g_argidx[c4]));
    const int jm0 = idx.x >> 7, jm1 = idx.y >> 7, jm2 = idx.z >> 7, jm3 = idx.w >> 7;
    const float fb0 = 1.0f - (float)abs(i - (idx.x & 127)) * inv_n;
    const float fb1 = 1.0f - (float)abs(i - (idx.y & 127)) * inv_n;
    const float fb2 = 1.0f - (float)abs(i - (idx.z & 127)) * inv_n;
    const float fb3 = 1.0f - (float)abs(i - (idx.w & 127)) * inv_n;

    const float4* __restrict__ xp =
        reinterpret_cast<const float4*>(x + (size_t)p0 * DEPTH + c4);
    float4* __restrict__ op =
        reinterpret_cast<float4*>(out + (size_t)p0 * DEPTH + c4);
    const int stride4 = DEPTH / 4;

    for (int pb = 0; pb < P3_PS; pb += P3_BATCH) {
        float4 buf[P3_BATCH];
        #pragma unroll
        for (int u = 0; u < P3_BATCH; u++)
            buf[u] = __ldg(xp + (size_t)(pb + u) * stride4);

        #pragma unroll
        for (int u = 0; u < P3_BATCH; u++) {
            const int j = j0 + pb + u;
            float k0 = fmaxf(-1.0f, fb0 - (float)abs(j - jm0) * inv_n);
            float k1 = fmaxf(-1.0f, fb1 - (float)abs(j - jm1) * inv_n);
            float k2 = fmaxf(-1.0f, fb2 - (float)abs(j - jm2) * inv_n);
            float k3 = fmaxf(-1.0f, fb3 - (float)abs(j - jm3) * inv_n);
            float4 o;
            o.x = buf[u].x * k0;
            o.y = buf[u].y * k1;
            o.z = buf[u].z * k2;
            o.w = buf[u].w * k3;
            __stwt(op + (size_t)(pb + u) * stride4, o);   // write-through
        }
    }
}

extern "C" void kernel_launch(void* const* d_in, const int* in_sizes, int n_in,
                              void* d_out, int out_size)
{
    const float* x = (const float*)d_in[0];
    float* out = (float*)d_out;

    dim3 g1(CH_GROUPS, NCHUNK);
    partial_argmax_kernel<<<g1, P1_TPB>>>(x);

    reduce_argmax_stage1<<<(RGROUPS * DEPTH) / 256, 256>>>();
    reduce_argmax_stage2<<<DEPTH / 256, 256>>>();

    dim3 g3(CH_GROUPS, P3_NCHUNK);
    apply_mask_kernel<<<g3, P1_TPB>>>(x, out);
}

// round 6
// speedup vs baseline: 1.1446x; 1.1446x over previous
#include <cuda_runtime.h>
#include <math_constants.h>

// Shapes (fixed per reference setup_inputs)
#define N_SPATIAL 128
#define DEPTH     2048
#define NPOS      (N_SPATIAL * N_SPATIAL)     // 16384
#define TOTAL     (NPOS * DEPTH)

// Pass-1 tiling
#define NCHUNK    512
#define PS        (NPOS / NCHUNK)             // 32
#define P1_TPB    256
#define CH_PER_T  4
#define CH_GROUPS (DEPTH / (P1_TPB * CH_PER_T)) // 2
#define P1_BATCH  4

// Pass-3 tiling
#define P3_PS     32
#define P3_NCHUNK (NPOS / P3_PS)              // 512
#define P3_BATCH  8

// Packed argmax keys: (monotonic float bits << 32) | ~idx
// atomicMax picks the max value; among equal values, larger ~idx = smaller
// idx = first occurrence (jnp.argmax tie rule).
__device__ unsigned long long g_key[DEPTH];

__device__ __forceinline__ unsigned int float_orderable(float f)
{
    unsigned int u = __float_as_uint(f);
    return ((int)u < 0) ? ~u : (u | 0x80000000u);
}

// merge: a holds the SMALLER index -> '>=' keeps first occurrence
__device__ __forceinline__ void merge_ge(float& ma, int& ia, float mb, int ib)
{
    bool keep = (ma >= mb);
    ma = keep ? ma : mb;
    ia = keep ? ia : ib;
}

// ---------------------------------------------------------------------------
// Init: zero the keys (every replay, keeps kernel_launch deterministic).
// ---------------------------------------------------------------------------
__global__ void init_keys_kernel(void)
{
    g_key[blockIdx.x * blockDim.x + threadIdx.x] = 0ULL;
}

// ---------------------------------------------------------------------------
// Pass 1 (fused with reduce): per-(chunk, channel) local argmax over 32
// positions, then one packed atomicMax per channel. Forward order, default
// cached loads -> x allocates/retains in L2 for pass 3.
// ---------------------------------------------------------------------------
__global__ void __launch_bounds__(P1_TPB, 5)
partial_argmax_kernel(const float* __restrict__ x)
{
    const int chunk = blockIdx.y;
    const int c4 = (blockIdx.x * P1_TPB + threadIdx.x) * CH_PER_T;
    const int p0 = chunk * PS;

    float m0 = -CUDART_INF_F, m1 = -CUDART_INF_F, m2 = -CUDART_INF_F, m3 = -CUDART_INF_F;
    int i0 = 0, i1 = 0, i2 = 0, i3 = 0;

    const float4* __restrict__ xp =
        reinterpret_cast<const float4*>(x + (size_t)p0 * DEPTH + c4);
    const int stride4 = DEPTH / 4;

    for (int pb = 0; pb < PS; pb += P1_BATCH) {
        float4 b0 = __ldg(xp + (size_t)(pb + 0) * stride4);
        float4 b1 = __ldg(xp + (size_t)(pb + 1) * stride4);
        float4 b2 = __ldg(xp + (size_t)(pb + 2) * stride4);
        float4 b3 = __ldg(xp + (size_t)(pb + 3) * stride4);
        const int q0 = p0 + pb, q1 = q0 + 1, q2 = q0 + 2, q3 = q0 + 3;

        { float ma = b0.x; int ia = q0; merge_ge(ma, ia, b1.x, q1);
          float mb = b2.x; int ib = q2; merge_ge(mb, ib, b3.x, q3);
          merge_ge(ma, ia, mb, ib);
          if (ma > m0) { m0 = ma; i0 = ia; } }
        { float ma = b0.y; int ia = q0; merge_ge(ma, ia, b1.y, q1);
          float mb = b2.y; int ib = q2; merge_ge(mb, ib, b3.y, q3);
          merge_ge(ma, ia, mb, ib);
          if (ma > m1) { m1 = ma; i1 = ia; } }
        { float ma = b0.z; int ia = q0; merge_ge(ma, ia, b1.z, q1);
          float mb = b2.z; int ib = q2; merge_ge(mb, ib, b3.z, q3);
          merge_ge(ma, ia, mb, ib);
          if (ma > m2) { m2 = ma; i2 = ia; } }
        { float ma = b0.w; int ia = q0; merge_ge(ma, ia, b1.w, q1);
          float mb = b2.w; int ib = q2; merge_ge(mb, ib, b3.w, q3);
          merge_ge(ma, ia, mb, ib);
          if (ma > m3) { m3 = ma; i3 = ia; } }
    }

    atomicMax(&g_key[c4 + 0], ((unsigned long long)float_orderable(m0) << 32) | (unsigned int)(~i0));
    atomicMax(&g_key[c4 + 1], ((unsigned long long)float_orderable(m1) << 32) | (unsigned int)(~i1));
    atomicMax(&g_key[c4 + 2], ((unsigned long long)float_orderable(m2) << 32) | (unsigned int)(~i2));
    atomicMax(&g_key[c4 + 3], ((unsigned long long)float_orderable(m3) << 32) | (unsigned int)(~i3));
}

// ---------------------------------------------------------------------------
// Pass 3: out = x * max(-1, 1 - l1/128) with the reference's transposed
// coords (i_max = idx % 128, j_max = idx / 128).
// REVERSE chunk order: reads the addresses pass 1 cached most recently ->
// best shot at L2 hits. __ldg reads (re-allocate, keep x resident across
// graph replays), __stcs stores (evict-first, don't churn x out of L2).
// ---------------------------------------------------------------------------
__global__ void __launch_bounds__(P1_TPB)
apply_mask_kernel(const float* __restrict__ x, float* __restrict__ out)
{
    const int chunk = (P3_NCHUNK - 1) - blockIdx.y;     // reversed
    const int c4 = (blockIdx.x * P1_TPB + threadIdx.x) * CH_PER_T;
    const int p0 = chunk * P3_PS;
    const int i  = p0 >> 7;                             // row (constant in chunk)
    const int j0 = p0 & 127;                            // starting col

    const float inv_n = 1.0f / (float)N_SPATIAL;

    // decode argmax indices for the 4 owned channels
    ulonglong2 k01 = *reinterpret_cast<const ulonglong2*>(&g_key[c4]);
    ulonglong2 k23 = *reinterpret_cast<const ulonglong2*>(&g_key[c4 + 2]);
    const int idx0 = (int)(~(unsigned int)k01.x) & 0x3FFF;
    const int idx1 = (int)(~(unsigned int)k01.y) & 0x3FFF;
    const int idx2 = (int)(~(unsigned int)k23.x) & 0x3FFF;
    const int idx3 = (int)(~(unsigned int)k23.y) & 0x3FFF;

    const int jm0 = idx0 >> 7, jm1 = idx1 >> 7, jm2 = idx2 >> 7, jm3 = idx3 >> 7;
    const float fb0 = 1.0f - (float)abs(i - (idx0 & 127)) * inv_n;
    const float fb1 = 1.0f - (float)abs(i - (idx1 & 127)) * inv_n;
    const float fb2 = 1.0f - (float)abs(i - (idx2 & 127)) * inv_n;
    const float fb3 = 1.0f - (float)abs(i - (idx3 & 127)) * inv_n;

    const float4* __restrict__ xp =
        reinterpret_cast<const float4*>(x + (size_t)p0 * DEPTH + c4);
    float4* __restrict__ op =
        reinterpret_cast<float4*>(out + (size_t)p0 * DEPTH + c4);
    const int stride4 = DEPTH / 4;

    for (int pb = 0; pb < P3_PS; pb += P3_BATCH) {
        float4 buf[P3_BATCH];
        #pragma unroll
        for (int u = 0; u < P3_BATCH; u++)
            buf[u] = __ldg(xp + (size_t)(pb + u) * stride4);

        #pragma unroll
        for (int u = 0; u < P3_BATCH; u++) {
            const int j = j0 + pb + u;
            float k0 = fmaxf(-1.0f, fb0 - (float)abs(j - jm0) * inv_n);
            float k1 = fmaxf(-1.0f, fb1 - (float)abs(j - jm1) * inv_n);
            float k2 = fmaxf(-1.0f, fb2 - (float)abs(j - jm2) * inv_n);
            float k3 = fmaxf(-1.0f, fb3 - (float)abs(j - jm3) * inv_n);
            float4 o;
            o.x = buf[u].x * k0;
            o.y = buf[u].y * k1;
            o.z = buf[u].z * k2;
            o.w = buf[u].w * k3;
            __stcs(op + (size_t)(pb + u) * stride4, o);
        }
    }
}

extern "C" void kernel_launch(void* const* d_in, const int* in_sizes, int n_in,
                              void* d_out, int out_size)
{
    const float* x = (const float*)d_in[0];
    float* out = (float*)d_out;

    init_keys_kernel<<<DEPTH / 256, 256>>>();

    dim3 g1(CH_GROUPS, NCHUNK);
    partial_argmax_kernel<<<g1, P1_TPB>>>(x);

    dim3 g3(CH_GROUPS, P3_NCHUNK);
    apply_mask_kernel<<<g3, P1_TPB>>>(x, out);
}